// round 5
// baseline (speedup 1.0000x reference)
#include <cuda_runtime.h>
#include <cstdint>

#define D_DIM 4096
#define TPB   512
#define EPT   8   // elements per thread (512*8 = 4096)

// ---------------- Threefry-2x32 (JAX 20-round schedule), host scalar ----------------

static inline uint32_t rotl_host(uint32_t x, int r) { return (x << r) | (x >> (32 - r)); }

static void tf2x32_host(uint32_t k1, uint32_t k2, uint32_t x0, uint32_t x1,
                        uint32_t& o0, uint32_t& o1) {
    const uint32_t ks2 = k1 ^ k2 ^ 0x1BD11BDAu;
    x0 += k1; x1 += k2;
#define TF_RH(r) { x0 += x1; x1 = rotl_host(x1, (r)); x1 ^= x0; }
    TF_RH(13) TF_RH(15) TF_RH(26) TF_RH(6)   x0 += k2;  x1 += ks2 + 1u;
    TF_RH(17) TF_RH(29) TF_RH(16) TF_RH(24)  x0 += ks2; x1 += k1  + 2u;
    TF_RH(13) TF_RH(15) TF_RH(26) TF_RH(6)   x0 += k1;  x1 += k2  + 3u;
    TF_RH(17) TF_RH(29) TF_RH(16) TF_RH(24)  x0 += k2;  x1 += ks2 + 4u;
    TF_RH(13) TF_RH(15) TF_RH(26) TF_RH(6)   x0 += ks2; x1 += k1  + 5u;
#undef TF_RH
    o0 = x0; o1 = x1;
}

// Device scalar version (used once per block for the randint draw)
__device__ __forceinline__ void tf2x32_dev(uint32_t k1, uint32_t k2,
                                           uint32_t x0, uint32_t x1,
                                           uint32_t& o0, uint32_t& o1) {
    const uint32_t ks2 = k1 ^ k2 ^ 0x1BD11BDAu;
    x0 += k1; x1 += k2;
#define TF_R(r) { x0 += x1; x1 = __funnelshift_l(x1, x1, (r)); x1 ^= x0; }
    TF_R(13) TF_R(15) TF_R(26) TF_R(6)   x0 += k2;  x1 += ks2 + 1u;
    TF_R(17) TF_R(29) TF_R(16) TF_R(24)  x0 += ks2; x1 += k1  + 2u;
    TF_R(13) TF_R(15) TF_R(26) TF_R(6)   x0 += k1;  x1 += k2  + 3u;
    TF_R(17) TF_R(29) TF_R(16) TF_R(24)  x0 += k2;  x1 += ks2 + 4u;
    TF_R(13) TF_R(15) TF_R(26) TF_R(6)   x0 += ks2; x1 += k1  + 5u;
#undef TF_R
    o0 = x0; o1 = x1;
}

// ---------------- Kernel: one CTA per row ----------------

__global__ __launch_bounds__(TPB)
void nade_mask_kernel(const float* __restrict__ x, float* __restrict__ out,
                      uint32_t kp0, uint32_t kp1,   // k_perm  (uniform scores)
                      uint32_t s20, uint32_t s21) { // randint lower-bits key
    __shared__ uint32_t hist[D_DIM];     // count -> (count<<24)|excl_prefix
    __shared__ uint32_t scat[D_DIM];     // scattered composite keys
    __shared__ float    mskf[D_DIM];     // final per-position mask (1.0f / 0.0f)
    __shared__ uint32_t wsum[TPB / 32];
    __shared__ uint32_t s_n;

    const int t = threadIdx.x;
    const uint32_t b = blockIdx.x;

    {   // vectorized zeroing of hist
        uint4 z = make_uint4(0u, 0u, 0u, 0u);
        uint4* h4 = reinterpret_cast<uint4*>(hist);
#pragma unroll
        for (int k = 0; k < D_DIM / 4 / TPB; k++) h4[k * TPB + t] = z;
    }
    if (t == 0) {
        uint32_t o0, o1;
        tf2x32_dev(s20, s21, 0u, b, o0, o1);
        s_n = (o0 ^ o1) & (D_DIM - 1u);   // span=4096 power of two -> bits & 4095
    }
    __syncthreads();

    // ---- Phase 1: 8 threefry chains interleaved; ONE atomic pass.
    // The atomicAdd return value is a unique within-bucket arrival index p
    // (0..count-1); pack the eight 8-bit p's into 2 registers.
    uint32_t m_[EPT];
    uint32_t pp0 = 0u, pp1 = 0u;
    {
        uint32_t X0[EPT], X1[EPT];
        const uint32_t ks2 = kp0 ^ kp1 ^ 0x1BD11BDAu;
        const uint32_t fbase = b * (uint32_t)D_DIM + (uint32_t)t * EPT;
#pragma unroll
        for (int e = 0; e < EPT; e++) { X0[e] = kp0; X1[e] = (fbase + (uint32_t)e) + kp1; }
#define R8(r) _Pragma("unroll") \
        for (int e = 0; e < EPT; e++) { X0[e] += X1[e]; \
            X1[e] = __funnelshift_l(X1[e], X1[e], (r)); X1[e] ^= X0[e]; }
#define INJ8(a, bb) _Pragma("unroll") \
        for (int e = 0; e < EPT; e++) { X0[e] += (a); X1[e] += (bb); }
        R8(13) R8(15) R8(26) R8(6)   INJ8(kp1, ks2 + 1u)
        R8(17) R8(29) R8(16) R8(24)  INJ8(ks2, kp0 + 2u)
        R8(13) R8(15) R8(26) R8(6)   INJ8(kp0, kp1 + 3u)
        R8(17) R8(29) R8(16) R8(24)  INJ8(kp1, ks2 + 4u)
        R8(13) R8(15) R8(26) R8(6)   INJ8(ks2, kp0 + 5u)
#undef R8
#undef INJ8
#pragma unroll
        for (int e = 0; e < EPT; e++) {
            uint32_t m = (X0[e] ^ X1[e]) >> 9;   // 23-bit mantissa key
            m_[e] = m;
            uint32_t p = atomicAdd(&hist[m >> 11], 1u);   // arrival index
            if (e < 4) pp0 |= p << (8 * e);
            else       pp1 |= p << (8 * (e - 4));
        }
    }
    __syncthreads();

    // ---- Phase 2: exclusive scan of 4096 bins; pack (count<<24)|excl back into hist
    const int hb = t * EPT;
    uint4 h0 = *reinterpret_cast<uint4*>(&hist[hb]);
    uint4 h1 = *reinterpret_cast<uint4*>(&hist[hb + 4]);
    uint32_t c_[EPT] = {h0.x, h0.y, h0.z, h0.w, h1.x, h1.y, h1.z, h1.w};
    uint32_t loc[EPT], run = 0;
#pragma unroll
    for (int e = 0; e < EPT; e++) { loc[e] = run; run += c_[e]; }
    uint32_t v = run;
    const int lane = t & 31, wid = t >> 5;
#pragma unroll
    for (int d = 1; d < 32; d <<= 1) {
        uint32_t y = __shfl_up_sync(0xFFFFFFFFu, v, d);
        if (lane >= d) v += y;
    }
    if (lane == 31) wsum[wid] = v;
    __syncthreads();
    if (t == 0) {
        uint32_t acc = 0;
#pragma unroll
        for (int i = 0; i < TPB / 32; i++) { uint32_t c = wsum[i]; wsum[i] = acc; acc += c; }
    }
    __syncthreads();
    const uint32_t texcl = wsum[wid] + (v - run);
    h0.x = (c_[0] << 24) | (texcl + loc[0]);
    h0.y = (c_[1] << 24) | (texcl + loc[1]);
    h0.z = (c_[2] << 24) | (texcl + loc[2]);
    h0.w = (c_[3] << 24) | (texcl + loc[3]);
    h1.x = (c_[4] << 24) | (texcl + loc[4]);
    h1.y = (c_[5] << 24) | (texcl + loc[5]);
    h1.z = (c_[6] << 24) | (texcl + loc[6]);
    h1.w = (c_[7] << 24) | (texcl + loc[7]);
    *reinterpret_cast<uint4*>(&hist[hb]) = h0;
    *reinterpret_cast<uint4*>(&hist[hb + 4]) = h1;
    __syncthreads();

    // ---- Phase 3: scatter composite keys (no atomics: slot = seg_start + p)
#pragma unroll
    for (int e = 0; e < EPT; e++) {
        const uint32_t m = m_[e];
        const uint32_t p = (e < 4) ? ((pp0 >> (8 * e)) & 0xFFu)
                                   : ((pp1 >> (8 * (e - 4))) & 0xFFu);
        const uint32_t start = hist[m >> 11] & 0x00FFFFFFu;
        scat[start + p] = ((m & 0x7FFu) << 12) | (uint32_t)(t * EPT + e);
    }
    __syncthreads();

    // ---- Phase 4: within-bucket stable rank + float mask write
    const uint32_t n = s_n;
#pragma unroll
    for (int e = 0; e < EPT; e++) {
        const uint32_t idx = (uint32_t)(t * EPT + e);
        const uint32_t m = m_[e];
        const uint32_t w = hist[m >> 11];
        const uint32_t c = w >> 24;
        const uint32_t start = w & 0x00FFFFFFu;
        uint32_t rank = start;
        if (c > 1) {
            const uint32_t packed = ((m & 0x7FFu) << 12) | idx;
            for (uint32_t q = start; q < start + c; q++)
                rank += (scat[q] < packed) ? 1u : 0u;
        }
        mskf[rank] = (idx < n) ? 1.0f : 0.0f;
    }
    __syncthreads();

    // ---- Phase 5: stream output (float4; mask already float)
    const float4* x4 = reinterpret_cast<const float4*>(x) + (size_t)b * (D_DIM / 4);
    float4* o4 = reinterpret_cast<float4*>(out) + (size_t)b * (2 * D_DIM / 4);
    const float4* mf4 = reinterpret_cast<const float4*>(mskf);
#pragma unroll
    for (int k = 0; k < D_DIM / 4 / TPB; k++) {
        const int i = k * TPB + t;
        const float4 mv = mf4[i];
        const float4 xv = x4[i];
        o4[i] = make_float4(xv.x * mv.x, xv.y * mv.y, xv.z * mv.z, xv.w * mv.w);
        o4[D_DIM / 4 + i] = mv;
    }
}

// ---------------- Launch ----------------

extern "C" void kernel_launch(void* const* d_in, const int* in_sizes, int n_in,
                              void* d_out, int out_size) {
    const float* x = (const float*)d_in[0];
    float* out = (float*)d_out;

    // Host-side JAX key chain (SEED = 42, threefry_partitionable fold-like split):
    //   root key K = (0, 42)
    //   k_ints = TF(K, (0,0)) ; k_perm = TF(K, (0,1))
    //   randint: (k1, k2) = split(k_ints); only k2 (lower bits) matters (span = 2^12)
    uint32_t ki0, ki1, kp0, kp1, s20, s21;
    tf2x32_host(0u, 42u, 0u, 0u, ki0, ki1);   // k_ints
    tf2x32_host(0u, 42u, 0u, 1u, kp0, kp1);   // k_perm
    tf2x32_host(ki0, ki1, 0u, 1u, s20, s21);  // second key of randint's inner split

    const int B = in_sizes[0] / D_DIM;        // 16384
    nade_mask_kernel<<<B, TPB>>>(x, out, kp0, kp1, s20, s21);
}

// round 6
// speedup vs baseline: 1.2465x; 1.2465x over previous
#include <cuda_runtime.h>
#include <cstdint>

#define D_DIM 4096
#define TPB   512
#define EPT   8   // elements per thread (512*8 = 4096)

// ---------------- Threefry-2x32 (JAX 20-round schedule), host scalar ----------------

static inline uint32_t rotl_host(uint32_t x, int r) { return (x << r) | (x >> (32 - r)); }

static void tf2x32_host(uint32_t k1, uint32_t k2, uint32_t x0, uint32_t x1,
                        uint32_t& o0, uint32_t& o1) {
    const uint32_t ks2 = k1 ^ k2 ^ 0x1BD11BDAu;
    x0 += k1; x1 += k2;
#define TF_RH(r) { x0 += x1; x1 = rotl_host(x1, (r)); x1 ^= x0; }
    TF_RH(13) TF_RH(15) TF_RH(26) TF_RH(6)   x0 += k2;  x1 += ks2 + 1u;
    TF_RH(17) TF_RH(29) TF_RH(16) TF_RH(24)  x0 += ks2; x1 += k1  + 2u;
    TF_RH(13) TF_RH(15) TF_RH(26) TF_RH(6)   x0 += k1;  x1 += k2  + 3u;
    TF_RH(17) TF_RH(29) TF_RH(16) TF_RH(24)  x0 += k2;  x1 += ks2 + 4u;
    TF_RH(13) TF_RH(15) TF_RH(26) TF_RH(6)   x0 += ks2; x1 += k1  + 5u;
#undef TF_RH
    o0 = x0; o1 = x1;
}

// Device scalar version (used once per block for the randint draw)
__device__ __forceinline__ void tf2x32_dev(uint32_t k1, uint32_t k2,
                                           uint32_t x0, uint32_t x1,
                                           uint32_t& o0, uint32_t& o1) {
    const uint32_t ks2 = k1 ^ k2 ^ 0x1BD11BDAu;
    x0 += k1; x1 += k2;
#define TF_R(r) { x0 += x1; x1 = __funnelshift_l(x1, x1, (r)); x1 ^= x0; }
    TF_R(13) TF_R(15) TF_R(26) TF_R(6)   x0 += k2;  x1 += ks2 + 1u;
    TF_R(17) TF_R(29) TF_R(16) TF_R(24)  x0 += ks2; x1 += k1  + 2u;
    TF_R(13) TF_R(15) TF_R(26) TF_R(6)   x0 += k1;  x1 += k2  + 3u;
    TF_R(17) TF_R(29) TF_R(16) TF_R(24)  x0 += k2;  x1 += ks2 + 4u;
    TF_R(13) TF_R(15) TF_R(26) TF_R(6)   x0 += ks2; x1 += k1  + 5u;
#undef TF_R
    o0 = x0; o1 = x1;
}

// ---------------- Kernel: one CTA per row ----------------
// __launch_bounds__(512, 3): pin 3 CTAs/SM (caps regs at 41) — R5 showed the
// same code at 51 regs drops to 2 CTAs/SM and loses 20% on issue utilization.

__global__ __launch_bounds__(TPB, 3)
void nade_mask_kernel(const float* __restrict__ x, float* __restrict__ out,
                      uint32_t kp0, uint32_t kp1,   // k_perm  (uniform scores)
                      uint32_t s20, uint32_t s21) { // randint lower-bits key
    __shared__ uint32_t hist[D_DIM];     // count -> (count<<24)|excl_prefix
    __shared__ uint32_t scat[D_DIM];     // scattered composite keys
    __shared__ float    mskf[D_DIM];     // final per-position mask (1.0f / 0.0f)
    __shared__ uint32_t wsum[TPB / 32];
    __shared__ uint32_t s_n;

    const int t = threadIdx.x;
    const uint32_t b = blockIdx.x;

    {   // vectorized zeroing of hist
        uint4 z = make_uint4(0u, 0u, 0u, 0u);
        uint4* h4 = reinterpret_cast<uint4*>(hist);
#pragma unroll
        for (int k = 0; k < D_DIM / 4 / TPB; k++) h4[k * TPB + t] = z;
    }
    if (t == 0) {
        uint32_t o0, o1;
        tf2x32_dev(s20, s21, 0u, b, o0, o1);
        s_n = (o0 ^ o1) & (D_DIM - 1u);   // span=4096 power of two -> bits & 4095
    }
    __syncthreads();

    // ---- Phase 1: 8 threefry chains interleaved; ONE atomic pass.
    // The atomicAdd return value is a unique within-bucket arrival index p
    // (0..count-1); pack the eight 8-bit p's into 2 registers.
    uint32_t m_[EPT];
    uint32_t pp0 = 0u, pp1 = 0u;
    {
        uint32_t X0[EPT], X1[EPT];
        const uint32_t ks2 = kp0 ^ kp1 ^ 0x1BD11BDAu;
        const uint32_t fbase = b * (uint32_t)D_DIM + (uint32_t)t * EPT;
#pragma unroll
        for (int e = 0; e < EPT; e++) { X0[e] = kp0; X1[e] = (fbase + (uint32_t)e) + kp1; }
#define R8(r) _Pragma("unroll") \
        for (int e = 0; e < EPT; e++) { X0[e] += X1[e]; \
            X1[e] = __funnelshift_l(X1[e], X1[e], (r)); X1[e] ^= X0[e]; }
#define INJ8(a, bb) _Pragma("unroll") \
        for (int e = 0; e < EPT; e++) { X0[e] += (a); X1[e] += (bb); }
        R8(13) R8(15) R8(26) R8(6)   INJ8(kp1, ks2 + 1u)
        R8(17) R8(29) R8(16) R8(24)  INJ8(ks2, kp0 + 2u)
        R8(13) R8(15) R8(26) R8(6)   INJ8(kp0, kp1 + 3u)
        R8(17) R8(29) R8(16) R8(24)  INJ8(kp1, ks2 + 4u)
        R8(13) R8(15) R8(26) R8(6)   INJ8(ks2, kp0 + 5u)
#undef R8
#undef INJ8
#pragma unroll
        for (int e = 0; e < EPT; e++) {
            uint32_t m = (X0[e] ^ X1[e]) >> 9;   // 23-bit mantissa key
            m_[e] = m;
            uint32_t p = atomicAdd(&hist[m >> 11], 1u);   // arrival index
            if (e < 4) pp0 |= p << (8 * e);
            else       pp1 |= p << (8 * (e - 4));
        }
    }
    __syncthreads();

    // ---- Phase 2: exclusive scan of 4096 bins; pack (count<<24)|excl back into hist
    const int hb = t * EPT;
    uint4 h0 = *reinterpret_cast<uint4*>(&hist[hb]);
    uint4 h1 = *reinterpret_cast<uint4*>(&hist[hb + 4]);
    uint32_t c_[EPT] = {h0.x, h0.y, h0.z, h0.w, h1.x, h1.y, h1.z, h1.w};
    uint32_t loc[EPT], run = 0;
#pragma unroll
    for (int e = 0; e < EPT; e++) { loc[e] = run; run += c_[e]; }
    uint32_t v = run;
    const int lane = t & 31, wid = t >> 5;
#pragma unroll
    for (int d = 1; d < 32; d <<= 1) {
        uint32_t y = __shfl_up_sync(0xFFFFFFFFu, v, d);
        if (lane >= d) v += y;
    }
    if (lane == 31) wsum[wid] = v;
    __syncthreads();
    if (t == 0) {
        uint32_t acc = 0;
#pragma unroll
        for (int i = 0; i < TPB / 32; i++) { uint32_t c = wsum[i]; wsum[i] = acc; acc += c; }
    }
    __syncthreads();
    const uint32_t texcl = wsum[wid] + (v - run);
    h0.x = (c_[0] << 24) | (texcl + loc[0]);
    h0.y = (c_[1] << 24) | (texcl + loc[1]);
    h0.z = (c_[2] << 24) | (texcl + loc[2]);
    h0.w = (c_[3] << 24) | (texcl + loc[3]);
    h1.x = (c_[4] << 24) | (texcl + loc[4]);
    h1.y = (c_[5] << 24) | (texcl + loc[5]);
    h1.z = (c_[6] << 24) | (texcl + loc[6]);
    h1.w = (c_[7] << 24) | (texcl + loc[7]);
    *reinterpret_cast<uint4*>(&hist[hb]) = h0;
    *reinterpret_cast<uint4*>(&hist[hb + 4]) = h1;
    __syncthreads();

    // ---- Phase 3: scatter composite keys (no atomics: slot = seg_start + p)
#pragma unroll
    for (int e = 0; e < EPT; e++) {
        const uint32_t m = m_[e];
        const uint32_t p = (e < 4) ? ((pp0 >> (8 * e)) & 0xFFu)
                                   : ((pp1 >> (8 * (e - 4))) & 0xFFu);
        const uint32_t start = hist[m >> 11] & 0x00FFFFFFu;
        scat[start + p] = ((m & 0x7FFu) << 12) | (uint32_t)(t * EPT + e);
    }
    __syncthreads();

    // ---- Phase 4: within-bucket stable rank + float mask write
    const uint32_t n = s_n;
#pragma unroll
    for (int e = 0; e < EPT; e++) {
        const uint32_t idx = (uint32_t)(t * EPT + e);
        const uint32_t m = m_[e];
        const uint32_t w = hist[m >> 11];
        const uint32_t c = w >> 24;
        const uint32_t start = w & 0x00FFFFFFu;
        uint32_t rank = start;
        if (c > 1) {
            const uint32_t packed = ((m & 0x7FFu) << 12) | idx;
            for (uint32_t q = start; q < start + c; q++)
                rank += (scat[q] < packed) ? 1u : 0u;
        }
        mskf[rank] = (idx < n) ? 1.0f : 0.0f;
    }
    __syncthreads();

    // ---- Phase 5: stream output (float4; mask already float)
    const float4* x4 = reinterpret_cast<const float4*>(x) + (size_t)b * (D_DIM / 4);
    float4* o4 = reinterpret_cast<float4*>(out) + (size_t)b * (2 * D_DIM / 4);
    const float4* mf4 = reinterpret_cast<const float4*>(mskf);
#pragma unroll
    for (int k = 0; k < D_DIM / 4 / TPB; k++) {
        const int i = k * TPB + t;
        const float4 mv = mf4[i];
        const float4 xv = x4[i];
        o4[i] = make_float4(xv.x * mv.x, xv.y * mv.y, xv.z * mv.z, xv.w * mv.w);
        o4[D_DIM / 4 + i] = mv;
    }
}

// ---------------- Launch ----------------

extern "C" void kernel_launch(void* const* d_in, const int* in_sizes, int n_in,
                              void* d_out, int out_size) {
    const float* x = (const float*)d_in[0];
    float* out = (float*)d_out;

    // Host-side JAX key chain (SEED = 42, threefry_partitionable fold-like split):
    //   root key K = (0, 42)
    //   k_ints = TF(K, (0,0)) ; k_perm = TF(K, (0,1))
    //   randint: (k1, k2) = split(k_ints); only k2 (lower bits) matters (span = 2^12)
    uint32_t ki0, ki1, kp0, kp1, s20, s21;
    tf2x32_host(0u, 42u, 0u, 0u, ki0, ki1);   // k_ints
    tf2x32_host(0u, 42u, 0u, 1u, kp0, kp1);   // k_perm
    tf2x32_host(ki0, ki1, 0u, 1u, s20, s21);  // second key of randint's inner split

    const int B = in_sizes[0] / D_DIM;        // 16384
    nade_mask_kernel<<<B, TPB>>>(x, out, kp0, kp1, s20, s21);
}